// round 1
// baseline (speedup 1.0000x reference)
#include <cuda_runtime.h>
#include <cuda_bf16.h>

#define D_MODEL 768
#define N_HEADS 12
#define HD      64
#define B_SZ    4
#define T_SEQ   2048

// Static device scratch (no allocations allowed).
__device__ float g_qkv[(size_t)B_SZ * T_SEQ * 3 * D_MODEL];   // [B,T,3D]  75.5 MB
__device__ float g_att[(size_t)B_SZ * T_SEQ * D_MODEL];       // [B,T,D]   25 MB

// ---------------------------------------------------------------------------
// SGEMM with bias: C[M,N] = A[M,K] @ B[K,N] + bias[N]
// 128x128 block tile, BK=8, 256 threads, 8x8 per-thread microtile split as
// rows {rm..rm+3, rm+64..rm+67} x cols {cn..cn+3, cn+64..cn+67} to keep
// float4 smem reads bank-conflict free.
// Requires M%128==0, N%128==0, K%8==0 (true for all our shapes).
// ---------------------------------------------------------------------------
__global__ __launch_bounds__(256) void sgemm_bias(
    const float* __restrict__ A, const float* __restrict__ Bm,
    const float* __restrict__ bias, float* __restrict__ C,
    int M, int N, int K)
{
    __shared__ float As[8][128];
    __shared__ float Bs[8][128];

    const int tid = threadIdx.x;
    const int bm = blockIdx.y, bn = blockIdx.x;

    const int rm = (tid >> 4) * 4;        // 0..60
    const int cn = (tid & 15) * 4;        // 0..60

    float acc[8][8];
#pragma unroll
    for (int i = 0; i < 8; i++)
#pragma unroll
        for (int j = 0; j < 8; j++) acc[i][j] = 0.0f;

    const int a_row  = tid >> 1;          // 0..127
    const int a_half = tid & 1;           // 0..1 (cols 0-3 / 4-7)
    const float* Aptr = A + (size_t)(bm * 128 + a_row) * K + a_half * 4;

    const int b_row = tid >> 5;           // 0..7
    const int b_c   = (tid & 31) * 4;     // 0..124
    const float* Bptr = Bm + (size_t)b_row * N + bn * 128 + b_c;

    for (int k0 = 0; k0 < K; k0 += 8) {
        float4 a4 = *(const float4*)(Aptr + k0);
        float4 b4 = *(const float4*)(Bptr + (size_t)k0 * N);
        __syncthreads();
        As[a_half * 4 + 0][a_row] = a4.x;
        As[a_half * 4 + 1][a_row] = a4.y;
        As[a_half * 4 + 2][a_row] = a4.z;
        As[a_half * 4 + 3][a_row] = a4.w;
        *(float4*)&Bs[b_row][b_c] = b4;
        __syncthreads();

#pragma unroll
        for (int k = 0; k < 8; k++) {
            float4 a0 = *(const float4*)&As[k][rm];
            float4 a1 = *(const float4*)&As[k][rm + 64];
            float4 b0 = *(const float4*)&Bs[k][cn];
            float4 b1 = *(const float4*)&Bs[k][cn + 64];
            float ar[8] = {a0.x, a0.y, a0.z, a0.w, a1.x, a1.y, a1.z, a1.w};
            float br[8] = {b0.x, b0.y, b0.z, b0.w, b1.x, b1.y, b1.z, b1.w};
#pragma unroll
            for (int i = 0; i < 8; i++)
#pragma unroll
                for (int j = 0; j < 8; j++)
                    acc[i][j] += ar[i] * br[j];
        }
    }

    // Epilogue: add bias, write float4s.
    const int col0 = bn * 128 + cn;
    float4 bia0, bia1;
    bia0 = *(const float4*)(bias + col0);
    bia1 = *(const float4*)(bias + col0 + 64);
#pragma unroll
    for (int ii = 0; ii < 2; ii++) {
#pragma unroll
        for (int i = 0; i < 4; i++) {
            int row = bm * 128 + rm + ii * 64 + i;
            float* Crow = C + (size_t)row * N + col0;
            int ai = ii * 4 + i;
            float4 r0, r1;
            r0.x = acc[ai][0] + bia0.x;
            r0.y = acc[ai][1] + bia0.y;
            r0.z = acc[ai][2] + bia0.z;
            r0.w = acc[ai][3] + bia0.w;
            r1.x = acc[ai][4] + bia1.x;
            r1.y = acc[ai][5] + bia1.y;
            r1.z = acc[ai][6] + bia1.z;
            r1.w = acc[ai][7] + bia1.w;
            *(float4*)(Crow)      = r0;
            *(float4*)(Crow + 64) = r1;
        }
    }
}

// ---------------------------------------------------------------------------
// Flash attention (causal), fp32 SIMT.
// Block = 128 queries of one (b, h). Thread t owns query row qt*128+t:
// q[64] and acc[64] live in registers. K/V streamed in 64-key smem tiles.
// Online softmax in chunks of 16 keys. All smem reads are warp-broadcast.
// ---------------------------------------------------------------------------
__global__ __launch_bounds__(128) void attn_kernel(
    const float* __restrict__ qkv, float* __restrict__ out)
{
    __shared__ float Ks[64 * 64];
    __shared__ float Vs[64 * 64];

    const int b = blockIdx.z, h = blockIdx.y, qt = blockIdx.x;
    const int tid = threadIdx.x;
    const int qg = qt * 128 + tid;

    const float scale = 0.125f;  // 1/sqrt(64)

    // Load this thread's query row, pre-scaled.
    float q[64];
    {
        const float4* qp = (const float4*)(qkv + (size_t)(b * T_SEQ + qg) * (3 * D_MODEL) + h * HD);
#pragma unroll
        for (int i = 0; i < 16; i++) {
            float4 v = qp[i];
            q[4 * i + 0] = v.x * scale;
            q[4 * i + 1] = v.y * scale;
            q[4 * i + 2] = v.z * scale;
            q[4 * i + 3] = v.w * scale;
        }
    }

    float acc[64];
#pragma unroll
    for (int i = 0; i < 64; i++) acc[i] = 0.0f;
    float m = -1e30f, l = 0.0f;

    const int kt_end = (qt * 128 + 127) >> 6;  // inclusive

    for (int kt = 0; kt <= kt_end; kt++) {
        __syncthreads();
        {
            const float* kbase = qkv + (size_t)(b * T_SEQ + kt * 64) * (3 * D_MODEL) + D_MODEL + h * HD;
            const float* vbase = kbase + D_MODEL;
#pragma unroll
            for (int i = 0; i < 8; i++) {
                int idx = tid + i * 128;        // 0..1023
                int row = idx >> 4;
                int c4  = (idx & 15) * 4;
                size_t goff = (size_t)row * (3 * D_MODEL) + c4;
                *(float4*)&Ks[row * 64 + c4] = *(const float4*)(kbase + goff);
                *(float4*)&Vs[row * 64 + c4] = *(const float4*)(vbase + goff);
            }
        }
        __syncthreads();

        const float4* Ks4 = (const float4*)Ks;
        const float4* Vs4 = (const float4*)Vs;

#pragma unroll 1
        for (int c = 0; c < 4; c++) {
            const int j0 = kt * 64 + c * 16;
            if (j0 > qg) break;  // all later chunks masked for this query

            float s[16];
#pragma unroll
            for (int jj = 0; jj < 16; jj++) {
                const float4* kr = Ks4 + (c * 16 + jj) * 16;
                float sum = 0.0f;
#pragma unroll
                for (int d = 0; d < 16; d++) {
                    float4 kv = kr[d];
                    sum += q[4 * d + 0] * kv.x + q[4 * d + 1] * kv.y
                         + q[4 * d + 2] * kv.z + q[4 * d + 3] * kv.w;
                }
                s[jj] = (j0 + jj <= qg) ? sum : -1e30f;
            }

            float cmax = s[0];
#pragma unroll
            for (int jj = 1; jj < 16; jj++) cmax = fmaxf(cmax, s[jj]);
            float mnew = fmaxf(m, cmax);
            float corr = __expf(m - mnew);

            float p[16];
            float psum = 0.0f;
#pragma unroll
            for (int jj = 0; jj < 16; jj++) {
                p[jj] = __expf(s[jj] - mnew);
                psum += p[jj];
            }
            l = l * corr + psum;
#pragma unroll
            for (int i = 0; i < 64; i++) acc[i] *= corr;

#pragma unroll
            for (int jj = 0; jj < 16; jj++) {
                float pv = p[jj];
                const float4* vr = Vs4 + (c * 16 + jj) * 16;
#pragma unroll
                for (int d = 0; d < 16; d++) {
                    float4 vv = vr[d];
                    acc[4 * d + 0] += pv * vv.x;
                    acc[4 * d + 1] += pv * vv.y;
                    acc[4 * d + 2] += pv * vv.z;
                    acc[4 * d + 3] += pv * vv.w;
                }
            }
            m = mnew;
        }
    }

    const float inv = 1.0f / l;
    float* op = out + (size_t)(b * T_SEQ + qg) * D_MODEL + h * HD;
#pragma unroll
    for (int d = 0; d < 16; d++) {
        float4 r;
        r.x = acc[4 * d + 0] * inv;
        r.y = acc[4 * d + 1] * inv;
        r.z = acc[4 * d + 2] * inv;
        r.w = acc[4 * d + 3] * inv;
        *(float4*)(op + 4 * d) = r;
    }
}

// ---------------------------------------------------------------------------
extern "C" void kernel_launch(void* const* d_in, const int* in_sizes, int n_in,
                              void* d_out, int out_size)
{
    const float* x    = (const float*)d_in[0];
    const float* Wqkv = (const float*)d_in[1];
    const float* bqkv = (const float*)d_in[2];
    const float* Wo   = (const float*)d_in[3];
    const float* bo   = (const float*)d_in[4];
    float* out = (float*)d_out;

    float *qkv, *att;
    cudaGetSymbolAddress((void**)&qkv, g_qkv);
    cudaGetSymbolAddress((void**)&att, g_att);

    const int M = B_SZ * T_SEQ;  // 8192

    // 1) QKV projection: [8192,768] @ [768,2304] + b
    sgemm_bias<<<dim3((3 * D_MODEL) / 128, M / 128), 256>>>(
        x, Wqkv, bqkv, qkv, M, 3 * D_MODEL, D_MODEL);

    // 2) Causal flash attention -> [B,T,D]
    attn_kernel<<<dim3(T_SEQ / 128, N_HEADS, B_SZ), 128>>>(qkv, att);

    // 3) Output projection: [8192,768] @ [768,768] + b
    sgemm_bias<<<dim3(D_MODEL / 128, M / 128), 256>>>(
        att, Wo, bo, out, M, D_MODEL, D_MODEL);
}

// round 2
// speedup vs baseline: 3.1646x; 3.1646x over previous
#include <cuda_runtime.h>
#include <cuda_bf16.h>

#define D_MODEL 768
#define N_HEADS 12
#define HD      64
#define B_SZ    4
#define T_SEQ   2048

// Static device scratch (no allocations allowed).
__device__ float g_qkv[(size_t)B_SZ * T_SEQ * 3 * D_MODEL];   // [B,T,3D]
__device__ float g_att[(size_t)B_SZ * T_SEQ * D_MODEL];       // [B,T,D]

// ---------------------------------------------------------------------------
// Helpers: bf16 split-precision mma (x = hi + lo; x*y ~= hh + hl + lh)
// ---------------------------------------------------------------------------
__device__ __forceinline__ void mma_bf16(float c[4], const unsigned a[4],
                                         unsigned b0, unsigned b1)
{
    asm volatile(
        "mma.sync.aligned.m16n8k16.row.col.f32.bf16.bf16.f32 "
        "{%0,%1,%2,%3}, {%4,%5,%6,%7}, {%8,%9}, {%0,%1,%2,%3};\n"
        : "+f"(c[0]), "+f"(c[1]), "+f"(c[2]), "+f"(c[3])
        : "r"(a[0]), "r"(a[1]), "r"(a[2]), "r"(a[3]), "r"(b0), "r"(b1));
}

__device__ __forceinline__ unsigned pack_bf2(float e_lo, float e_hi)
{
    __nv_bfloat162 t = __floats2bfloat162_rn(e_lo, e_hi); // .x -> low half
    return *reinterpret_cast<unsigned*>(&t);
}

// Split a pair of consecutive-K fp32 values into hi/lo packed bf16x2.
__device__ __forceinline__ void split2(float x0, float x1, unsigned& hi, unsigned& lo)
{
    float h0 = __bfloat162float(__float2bfloat16(x0));
    float h1 = __bfloat162float(__float2bfloat16(x1));
    hi = pack_bf2(h0, h1);
    lo = pack_bf2(x0 - h0, x1 - h1);
}

// ---------------------------------------------------------------------------
// GEMM (split bf16 tensor-core): C[M,N] = A[M,K] @ B[K,N] + bias[N]
// 256 threads = 8 warps (4x2), block tile 128x128, warp tile 32x64, BK=32.
// Smem planes: AH/AL [128][20] u32 (k-pairs), BH/BL [16][136] u32 (k-pairs).
// Requires M%128==0, N%128==0, K%32==0.
// ---------------------------------------------------------------------------
__global__ __launch_bounds__(256) void gemm_bf16x2(
    const float* __restrict__ A, const float* __restrict__ Bm,
    const float* __restrict__ bias, float* __restrict__ C,
    int M, int N, int K)
{
    __shared__ unsigned AH[128 * 20];
    __shared__ unsigned AL[128 * 20];
    __shared__ unsigned BH[16 * 136];
    __shared__ unsigned BL[16 * 136];

    const int tid  = threadIdx.x;
    const int lane = tid & 31;
    const int wid  = tid >> 5;
    const int wm   = wid >> 1;      // 0..3 -> 32-row slabs
    const int wn   = wid & 1;       // 0..1 -> 64-col slabs
    const int lq   = lane >> 2;     // groupID
    const int lr   = lane & 3;      // thread-in-group
    const int bm = blockIdx.y, bn = blockIdx.x;

    float acc[2][8][4];
#pragma unroll
    for (int mt = 0; mt < 2; mt++)
#pragma unroll
        for (int n = 0; n < 8; n++)
#pragma unroll
            for (int j = 0; j < 4; j++) acc[mt][n][j] = 0.0f;

    const float* Ag = A + (size_t)(bm * 128) * K;
    const float* Bg = Bm + bn * 128;

    for (int k0 = 0; k0 < K; k0 += 32) {
        __syncthreads();
        // --- load A tile 128x32, split into hi/lo k-pair planes
#pragma unroll
        for (int i = 0; i < 4; i++) {
            int idx = tid + i * 256;          // 0..1023 over 128 rows x 8 float4
            int row = idx >> 3, c4 = (idx & 7) * 4;
            float4 v = *(const float4*)(Ag + (size_t)row * K + k0 + c4);
            unsigned h01, l01, h23, l23;
            split2(v.x, v.y, h01, l01);
            split2(v.z, v.w, h23, l23);
            int o = row * 20 + (c4 >> 1);
            AH[o] = h01; AH[o + 1] = h23;
            AL[o] = l01; AL[o + 1] = l23;
        }
        // --- load B tile 32x128, pack pairs along K
#pragma unroll
        for (int i = 0; i < 2; i++) {
            int idx = tid + i * 256;          // 0..511 over 16 kp x 32 float4
            int kp = idx >> 5, c4 = (idx & 31) * 4;
            const float* r0p = Bg + (size_t)(k0 + 2 * kp) * N + c4;
            const float* r1p = r0p + N;
            float4 v0 = *(const float4*)r0p;
            float4 v1 = *(const float4*)r1p;
            unsigned h[4], l[4];
            split2(v0.x, v1.x, h[0], l[0]);
            split2(v0.y, v1.y, h[1], l[1]);
            split2(v0.z, v1.z, h[2], l[2]);
            split2(v0.w, v1.w, h[3], l[3]);
            int o = kp * 136 + c4;
            *(uint4*)&BH[o] = make_uint4(h[0], h[1], h[2], h[3]);
            *(uint4*)&BL[o] = make_uint4(l[0], l[1], l[2], l[3]);
        }
        __syncthreads();

#pragma unroll
        for (int kk = 0; kk < 2; kk++) {      // two m16n8k16 steps per BK=32
            unsigned ah[2][4], al[2][4];
#pragma unroll
            for (int mt = 0; mt < 2; mt++) {
                int r = wm * 32 + mt * 16 + lq;
                int p = kk * 8 + lr;
                ah[mt][0] = AH[r * 20 + p];
                ah[mt][1] = AH[(r + 8) * 20 + p];
                ah[mt][2] = AH[r * 20 + p + 4];
                ah[mt][3] = AH[(r + 8) * 20 + p + 4];
                al[mt][0] = AL[r * 20 + p];
                al[mt][1] = AL[(r + 8) * 20 + p];
                al[mt][2] = AL[r * 20 + p + 4];
                al[mt][3] = AL[(r + 8) * 20 + p + 4];
            }
#pragma unroll
            for (int n = 0; n < 8; n++) {
                int col = wn * 64 + n * 8 + lq;
                unsigned bh0 = BH[(kk * 8 + lr) * 136 + col];
                unsigned bh1 = BH[(kk * 8 + lr + 4) * 136 + col];
                unsigned bl0 = BL[(kk * 8 + lr) * 136 + col];
                unsigned bl1 = BL[(kk * 8 + lr + 4) * 136 + col];
#pragma unroll
                for (int mt = 0; mt < 2; mt++) {
                    mma_bf16(acc[mt][n], ah[mt], bh0, bh1);
                    mma_bf16(acc[mt][n], ah[mt], bl0, bl1);
                    mma_bf16(acc[mt][n], al[mt], bh0, bh1);
                }
            }
        }
    }

    // --- epilogue: bias + store
#pragma unroll
    for (int mt = 0; mt < 2; mt++) {
        int r0 = bm * 128 + wm * 32 + mt * 16 + lq;
#pragma unroll
        for (int n = 0; n < 8; n++) {
            int col = bn * 128 + wn * 64 + n * 8 + 2 * lr;
            float b0 = bias[col], b1 = bias[col + 1];
            float2 v0 = make_float2(acc[mt][n][0] + b0, acc[mt][n][1] + b1);
            float2 v1 = make_float2(acc[mt][n][2] + b0, acc[mt][n][3] + b1);
            *(float2*)&C[(size_t)r0 * N + col]       = v0;
            *(float2*)&C[(size_t)(r0 + 8) * N + col] = v1;
        }
    }
}

// ---------------------------------------------------------------------------
// Flash attention (causal) on tensor cores, split-bf16.
// Block = 128 threads (4 warps), Q tile of 64 rows for one (b,h); warp w owns
// q rows [w*16, w*16+16). K/V tiles of 64 keys staged in smem as hi/lo bf16
// pair planes. P round-trips through smem (hi/lo) for the PV mma.
// Dynamic smem layout (u32):
//   KH[64*36] KL[64*36] VH[32*72] VL[32*72] PH[64*36] PL[64*36] = 13824 u32
// ---------------------------------------------------------------------------
#define AT_SK 36   // K/Q/P pair-plane stride (32 pairs + 4 pad)
#define AT_SV 72   // V pair-plane stride (64 + 8 pad)
#define ATTN_SMEM ((2*64*AT_SK + 2*32*AT_SV + 2*64*AT_SK) * 4)

__global__ __launch_bounds__(128) void attn_tc(
    const float* __restrict__ qkv, float* __restrict__ out)
{
    extern __shared__ unsigned usm[];
    unsigned* KH = usm;
    unsigned* KL = usm + 64 * AT_SK;
    unsigned* VH = usm + 2 * 64 * AT_SK;
    unsigned* VL = VH + 32 * AT_SV;
    unsigned* PH = VL + 32 * AT_SV;
    unsigned* PL = PH + 64 * AT_SK;

    const int b = blockIdx.z, h = blockIdx.y;
    const int qt = gridDim.x - 1 - blockIdx.x;   // heavy tiles first
    const int tid = threadIdx.x;
    const int w = tid >> 5, lane = tid & 31;
    const int lq = lane >> 2, lr = lane & 3;
    const float scale = 0.125f;                  // 1/sqrt(64)

    // ---- stage Q tile (scaled) into KH/KL, then read A-fragments
    {
        const float* qbase = qkv + ((size_t)(b * T_SEQ) + qt * 64) * (3 * D_MODEL) + h * HD;
#pragma unroll
        for (int i = 0; i < 8; i++) {
            int idx = tid + i * 128;             // 64 rows x 16 float4
            int row = idx >> 4, c4 = (idx & 15) * 4;
            float4 v = *(const float4*)(qbase + (size_t)row * (3 * D_MODEL) + c4);
            unsigned h01, l01, h23, l23;
            split2(v.x * scale, v.y * scale, h01, l01);
            split2(v.z * scale, v.w * scale, h23, l23);
            int o = row * AT_SK + (c4 >> 1);
            KH[o] = h01; KH[o + 1] = h23;
            KL[o] = l01; KL[o + 1] = l23;
        }
    }
    __syncthreads();

    unsigned qh[4][4], ql[4][4];
    {
        int r0 = w * 16 + lq;
#pragma unroll
        for (int kk = 0; kk < 4; kk++) {
            int p = kk * 8 + lr;
            qh[kk][0] = KH[r0 * AT_SK + p];
            qh[kk][1] = KH[(r0 + 8) * AT_SK + p];
            qh[kk][2] = KH[r0 * AT_SK + p + 4];
            qh[kk][3] = KH[(r0 + 8) * AT_SK + p + 4];
            ql[kk][0] = KL[r0 * AT_SK + p];
            ql[kk][1] = KL[(r0 + 8) * AT_SK + p];
            ql[kk][2] = KL[r0 * AT_SK + p + 4];
            ql[kk][3] = KL[(r0 + 8) * AT_SK + p + 4];
        }
    }

    float o_acc[8][4];
#pragma unroll
    for (int n = 0; n < 8; n++)
#pragma unroll
        for (int j = 0; j < 4; j++) o_acc[n][j] = 0.0f;
    float m0 = -1e30f, m1 = -1e30f, l0 = 0.0f, l1 = 0.0f;

    for (int kt = 0; kt <= qt; kt++) {
        __syncthreads();   // also protects Q staging on first iteration
        const float* kbase = qkv + ((size_t)(b * T_SEQ) + kt * 64) * (3 * D_MODEL) + D_MODEL + h * HD;
        const float* vbase = kbase + D_MODEL;
        // K tile: 64 keys x 64 d, pairs along d
#pragma unroll
        for (int i = 0; i < 8; i++) {
            int idx = tid + i * 128;
            int row = idx >> 4, c4 = (idx & 15) * 4;
            float4 v = *(const float4*)(kbase + (size_t)row * (3 * D_MODEL) + c4);
            unsigned h01, l01, h23, l23;
            split2(v.x, v.y, h01, l01);
            split2(v.z, v.w, h23, l23);
            int o = row * AT_SK + (c4 >> 1);
            KH[o] = h01; KH[o + 1] = h23;
            KL[o] = l01; KL[o + 1] = l23;
        }
        // V tile: pairs along key: 32 key-pairs x 64 d
#pragma unroll
        for (int i = 0; i < 4; i++) {
            int idx = tid + i * 128;             // 32 kp x 16 float4
            int kp = idx >> 4, c4 = (idx & 15) * 4;
            const float* r0p = vbase + (size_t)(2 * kp) * (3 * D_MODEL) + c4;
            const float* r1p = r0p + 3 * D_MODEL;
            float4 v0 = *(const float4*)r0p;
            float4 v1 = *(const float4*)r1p;
            unsigned hh[4], ll[4];
            split2(v0.x, v1.x, hh[0], ll[0]);
            split2(v0.y, v1.y, hh[1], ll[1]);
            split2(v0.z, v1.z, hh[2], ll[2]);
            split2(v0.w, v1.w, hh[3], ll[3]);
            int o = kp * AT_SV + c4;
            *(uint4*)&VH[o] = make_uint4(hh[0], hh[1], hh[2], hh[3]);
            *(uint4*)&VL[o] = make_uint4(ll[0], ll[1], ll[2], ll[3]);
        }
        __syncthreads();

        // ---- S = Q @ K^T
        float s[8][4];
#pragma unroll
        for (int n = 0; n < 8; n++)
#pragma unroll
            for (int j = 0; j < 4; j++) s[n][j] = 0.0f;
#pragma unroll
        for (int kk = 0; kk < 4; kk++) {
            int p = kk * 8 + lr;
#pragma unroll
            for (int n = 0; n < 8; n++) {
                int krow = n * 8 + lq;
                unsigned bh0 = KH[krow * AT_SK + p];
                unsigned bh1 = KH[krow * AT_SK + p + 4];
                unsigned bl0 = KL[krow * AT_SK + p];
                unsigned bl1 = KL[krow * AT_SK + p + 4];
                mma_bf16(s[n], qh[kk], bh0, bh1);
                mma_bf16(s[n], qh[kk], bl0, bl1);
                mma_bf16(s[n], ql[kk], bh0, bh1);
            }
        }

        // ---- causal mask (diagonal tile only)
        if (kt == qt) {
            int qr0 = w * 16 + lq;
#pragma unroll
            for (int n = 0; n < 8; n++) {
                int kc = n * 8 + 2 * lr;
                if (kc     > qr0)     s[n][0] = -1e30f;
                if (kc + 1 > qr0)     s[n][1] = -1e30f;
                if (kc     > qr0 + 8) s[n][2] = -1e30f;
                if (kc + 1 > qr0 + 8) s[n][3] = -1e30f;
            }
        }

        // ---- online softmax
        float rm0 = -1e30f, rm1 = -1e30f;
#pragma unroll
        for (int n = 0; n < 8; n++) {
            rm0 = fmaxf(rm0, fmaxf(s[n][0], s[n][1]));
            rm1 = fmaxf(rm1, fmaxf(s[n][2], s[n][3]));
        }
        rm0 = fmaxf(rm0, __shfl_xor_sync(0xffffffffu, rm0, 1));
        rm0 = fmaxf(rm0, __shfl_xor_sync(0xffffffffu, rm0, 2));
        rm1 = fmaxf(rm1, __shfl_xor_sync(0xffffffffu, rm1, 1));
        rm1 = fmaxf(rm1, __shfl_xor_sync(0xffffffffu, rm1, 2));
        float mn0 = fmaxf(m0, rm0), mn1 = fmaxf(m1, rm1);
        float c0 = __expf(m0 - mn0), c1 = __expf(m1 - mn1);
        m0 = mn0; m1 = mn1;

        int r0 = w * 16 + lq;
        float ps0 = 0.0f, ps1 = 0.0f;
#pragma unroll
        for (int n = 0; n < 8; n++) {
            float p00 = __expf(s[n][0] - mn0);
            float p01 = __expf(s[n][1] - mn0);
            float p10 = __expf(s[n][2] - mn1);
            float p11 = __expf(s[n][3] - mn1);
            ps0 += p00 + p01;
            ps1 += p10 + p11;
            unsigned hi, lo;
            split2(p00, p01, hi, lo);
            PH[r0 * AT_SK + n * 4 + lr] = hi;
            PL[r0 * AT_SK + n * 4 + lr] = lo;
            split2(p10, p11, hi, lo);
            PH[(r0 + 8) * AT_SK + n * 4 + lr] = hi;
            PL[(r0 + 8) * AT_SK + n * 4 + lr] = lo;
        }
        l0 = l0 * c0 + ps0;
        l1 = l1 * c1 + ps1;
#pragma unroll
        for (int n = 0; n < 8; n++) {
            o_acc[n][0] *= c0; o_acc[n][1] *= c0;
            o_acc[n][2] *= c1; o_acc[n][3] *= c1;
        }
        __syncwarp();

        // ---- O += P @ V
#pragma unroll
        for (int kk = 0; kk < 4; kk++) {
            int p = kk * 8 + lr;
            unsigned ah[4], al[4];
            ah[0] = PH[r0 * AT_SK + p];
            ah[1] = PH[(r0 + 8) * AT_SK + p];
            ah[2] = PH[r0 * AT_SK + p + 4];
            ah[3] = PH[(r0 + 8) * AT_SK + p + 4];
            al[0] = PL[r0 * AT_SK + p];
            al[1] = PL[(r0 + 8) * AT_SK + p];
            al[2] = PL[r0 * AT_SK + p + 4];
            al[3] = PL[(r0 + 8) * AT_SK + p + 4];
#pragma unroll
            for (int n = 0; n < 8; n++) {
                unsigned bh0 = VH[(kk * 8 + lr) * AT_SV + n * 8 + lq];
                unsigned bh1 = VH[(kk * 8 + lr + 4) * AT_SV + n * 8 + lq];
                unsigned bl0 = VL[(kk * 8 + lr) * AT_SV + n * 8 + lq];
                unsigned bl1 = VL[(kk * 8 + lr + 4) * AT_SV + n * 8 + lq];
                mma_bf16(o_acc[n], ah, bh0, bh1);
                mma_bf16(o_acc[n], ah, bl0, bl1);
                mma_bf16(o_acc[n], al, bh0, bh1);
            }
        }
        __syncwarp();
    }

    // ---- finalize: reduce l over quad, normalize, store
    l0 += __shfl_xor_sync(0xffffffffu, l0, 1);
    l0 += __shfl_xor_sync(0xffffffffu, l0, 2);
    l1 += __shfl_xor_sync(0xffffffffu, l1, 1);
    l1 += __shfl_xor_sync(0xffffffffu, l1, 2);
    float inv0 = 1.0f / l0, inv1 = 1.0f / l1;

    int qg0 = qt * 64 + w * 16 + lq;
    float* ob0 = out + ((size_t)(b * T_SEQ) + qg0) * D_MODEL + h * HD;
    float* ob1 = ob0 + (size_t)8 * D_MODEL;
#pragma unroll
    for (int n = 0; n < 8; n++) {
        int col = n * 8 + 2 * lr;
        *(float2*)(ob0 + col) = make_float2(o_acc[n][0] * inv0, o_acc[n][1] * inv0);
        *(float2*)(ob1 + col) = make_float2(o_acc[n][2] * inv1, o_acc[n][3] * inv1);
    }
}

// ---------------------------------------------------------------------------
extern "C" void kernel_launch(void* const* d_in, const int* in_sizes, int n_in,
                              void* d_out, int out_size)
{
    const float* x    = (const float*)d_in[0];
    const float* Wqkv = (const float*)d_in[1];
    const float* bqkv = (const float*)d_in[2];
    const float* Wo   = (const float*)d_in[3];
    const float* bo   = (const float*)d_in[4];
    float* out = (float*)d_out;

    float *qkv, *att;
    cudaGetSymbolAddress((void**)&qkv, g_qkv);
    cudaGetSymbolAddress((void**)&att, g_att);

    cudaFuncSetAttribute(attn_tc, cudaFuncAttributeMaxDynamicSharedMemorySize, ATTN_SMEM);

    const int M = B_SZ * T_SEQ;  // 8192

    // 1) QKV projection: [8192,768] @ [768,2304] + b
    gemm_bf16x2<<<dim3((3 * D_MODEL) / 128, M / 128), 256>>>(
        x, Wqkv, bqkv, qkv, M, 3 * D_MODEL, D_MODEL);

    // 2) Causal flash attention (tensor cores) -> [B,T,D]
    attn_tc<<<dim3(T_SEQ / 64, N_HEADS, B_SZ), 128, ATTN_SMEM>>>(qkv, att);

    // 3) Output projection: [8192,768] @ [768,768] + b
    gemm_bf16x2<<<dim3(D_MODEL / 128, M / 128), 256>>>(
        att, Wo, bo, out, M, D_MODEL, D_MODEL);
}